// round 9
// baseline (speedup 1.0000x reference)
#include <cuda_runtime.h>
#include <cuda_fp16.h>

#define NT  262144          /* B*H*S rows per tensor */
#define QS  136             /* smem row stride in halves */

__device__ __align__(16) float  g_P[2][16384];   /* partial Householder products */
__device__ __align__(16) __half g_Qhi[16384];

// ---------------------------------------------------------------------------
// Stage 1: two parallel 32-reflector partial products.
// ---------------------------------------------------------------------------
__global__ void build_p_kernel(const float* __restrict__ vs)
{
    __shared__ float svs[32 * 128];
    __shared__ float sinv[32];
    const int t = threadIdx.x;
    const int chunk = blockIdx.x >> 4;
    const float* vsrc = vs + chunk * 32 * 128;
    for (int i = t; i < 32 * 128; i += 128) svs[i] = vsrc[i];
    __syncthreads();
    if (t < 32) {
        float nn = 0.f;
#pragma unroll 8
        for (int i = 0; i < 128; i += 4) {
            const float4 v = *(const float4*)&svs[t * 128 + i];
            nn += v.x * v.x + v.y * v.y + v.z * v.z + v.w * v.w;
        }
        sinv[t] = 2.0f / (nn + 1e-8f);
    }
    __syncthreads();

    const int col = (blockIdx.x & 15) * 8 + (t >> 4);
    const int ip  = t & 15;
    float qc[8];
#pragma unroll
    for (int j = 0; j < 8; j++) qc[j] = (ip * 8 + j == col) ? 1.0f : 0.0f;

    for (int r = 0; r < 32; r++) {
        const float* v = &svs[r * 128 + ip * 8];
        float w = 0.f;
#pragma unroll
        for (int j = 0; j < 8; j++) w += v[j] * qc[j];
#pragma unroll
        for (int off = 8; off; off >>= 1) w += __shfl_xor_sync(0xffffffffu, w, off);
        const float sw = sinv[r] * w;
#pragma unroll
        for (int j = 0; j < 8; j++) qc[j] -= sw * v[j];
    }
#pragma unroll
    for (int j = 0; j < 8; j++) g_P[chunk][(ip * 8 + j) * 128 + col] = qc[j];
}

// ---------------------------------------------------------------------------
// Stage 2: Q = P2 * P1 (fp32), fused fp16 convert.
// ---------------------------------------------------------------------------
__global__ void combine_q_kernel()
{
    __shared__ float row2[128];
    const int i = blockIdx.x, j = threadIdx.x;
    row2[j] = g_P[1][i * 128 + j];
    __syncthreads();
    float s = 0.f;
#pragma unroll 8
    for (int e = 0; e < 128; e++) s += row2[e] * g_P[0][e * 128 + j];
    g_Qhi[i * 128 + j] = __float2half_rn(s);
}

// ---------------------------------------------------------------------------
__device__ __forceinline__ unsigned su32(const void* p)
{
    return (unsigned)__cvta_generic_to_shared(p);
}
__device__ __forceinline__ void ldsm4(unsigned r[4], unsigned a)
{
    asm volatile("ldmatrix.sync.aligned.m8n8.x4.shared.b16 {%0,%1,%2,%3}, [%4];\n"
                 : "=r"(r[0]), "=r"(r[1]), "=r"(r[2]), "=r"(r[3]) : "r"(a));
}
__device__ __forceinline__ void ldsm4t(unsigned r[4], unsigned a)
{
    asm volatile("ldmatrix.sync.aligned.m8n8.x4.trans.shared.b16 {%0,%1,%2,%3}, [%4];\n"
                 : "=r"(r[0]), "=r"(r[1]), "=r"(r[2]), "=r"(r[3]) : "r"(a));
}
__device__ __forceinline__ void mma16816(float c[4],
    unsigned a0, unsigned a1, unsigned a2, unsigned a3, unsigned b0, unsigned b1)
{
    asm volatile("mma.sync.aligned.m16n8k16.row.col.f32.f16.f16.f32 "
                 "{%0,%1,%2,%3}, {%4,%5,%6,%7}, {%8,%9}, {%0,%1,%2,%3};\n"
                 : "+f"(c[0]), "+f"(c[1]), "+f"(c[2]), "+f"(c[3])
                 : "r"(a0), "r"(a1), "r"(a2), "r"(a3), "r"(b0), "r"(b1));
}
__device__ __forceinline__ unsigned h2p(float a, float b)
{
    __half2 h = __floats2half2_rn(a, b);
    return *reinterpret_cast<unsigned*>(&h);
}

// ---------------------------------------------------------------------------
// Main kernel: 256 rows/CTA, 8 warps x (32 rows x 128 cols), single-pass fp16.
// 32 rows/warp -> each ldmatrix B-tile feeds 4 HMMA (halves LDSM traffic).
// 1 CTA/SM (255 regs). GEMM1 -> RoPE in regs -> pack fp16 -> GEMM2 -> store.
// ---------------------------------------------------------------------------
__global__ __launch_bounds__(256)
void rnrope_main(const float* __restrict__ qg, const float* __restrict__ kg,
                 const float* __restrict__ cosg, const float* __restrict__ sing,
                 float* __restrict__ out)
{
    __shared__ __align__(16) __half sQ[128 * QS];    /* 34816 B */

    const int tid = threadIdx.x;
    for (int i = tid; i < 128 * 16; i += 256) {
        const int row = i >> 4;
        const int ch  = (i & 15) * 8;
        *(uint4*)&sQ[row * QS + ch] = *(const uint4*)&g_Qhi[row * 128 + ch];
    }
    __syncthreads();

    const int warp = tid >> 5, lane = tid & 31;
    const int u = lane & 3, g = lane >> 2;

    const int base  = blockIdx.x * 256;                /* 2048 blocks */
    const int local = (base < NT) ? base : base - NT;  /* no q/k straddle */
    const float* x  = (base < NT) ? qg : kg;

    const int rb = local + warp * 32 + g;
    const float* A0 = x + (size_t)rb * 128;            /* m0 rows g, g+8   */
    const float* A1 = A0 + 8 * 128;
    const float* A2 = A0 + 16 * 128;                   /* m1 rows g+16,+24 */
    const float* A3 = A0 + 24 * 128;

    const int csr = ((local >> 17) << 13) + (local & 8191) + warp * 32 + g;
    const float* C0  = cosg + (size_t)csr * 128;
    const float* C1  = C0 + 8 * 128;
    const float* C2  = C0 + 16 * 128;
    const float* C3  = C0 + 24 * 128;
    const float* S0  = sing + (size_t)csr * 128;
    const float* S1  = S0 + 8 * 128;
    const float* S2  = S0 + 16 * 128;
    const float* S3  = S0 + 24 * 128;

    const int lbo = (((lane >> 4) << 3) + (lane & 7)) * QS + (((lane >> 3) & 1) << 3);

    float acc0[16][4], acc1[16][4];
#pragma unroll
    for (int n = 0; n < 16; n++)
#pragma unroll
        for (int i = 0; i < 4; i++) { acc0[n][i] = 0.f; acc1[n][i] = 0.f; }

    // ---------------- GEMM1: y = x @ Q^T ----------------
#pragma unroll
    for (int kt = 0; kt < 8; kt++) {
        const int co = kt * 16 + 2 * u;
        const float2 m00 = *(const float2*)&A0[co];
        const float2 m01 = *(const float2*)&A0[co + 8];
        const float2 m02 = *(const float2*)&A1[co];
        const float2 m03 = *(const float2*)&A1[co + 8];
        const float2 m10 = *(const float2*)&A2[co];
        const float2 m11 = *(const float2*)&A2[co + 8];
        const float2 m12 = *(const float2*)&A3[co];
        const float2 m13 = *(const float2*)&A3[co + 8];
        const unsigned a00 = h2p(m00.x, m00.y), a01 = h2p(m02.x, m02.y);
        const unsigned a02 = h2p(m01.x, m01.y), a03 = h2p(m03.x, m03.y);
        const unsigned a10 = h2p(m10.x, m10.y), a11 = h2p(m12.x, m12.y);
        const unsigned a12 = h2p(m11.x, m11.y), a13 = h2p(m13.x, m13.y);
#pragma unroll
        for (int np = 0; np < 8; np++) {
            unsigned bh[4];
            ldsm4(bh, su32(sQ + np * (16 * QS) + kt * 16 + lbo));
            mma16816(acc0[2 * np],     a00, a01, a02, a03, bh[0], bh[1]);
            mma16816(acc0[2 * np + 1], a00, a01, a02, a03, bh[2], bh[3]);
            mma16816(acc1[2 * np],     a10, a11, a12, a13, bh[0], bh[1]);
            mma16816(acc1[2 * np + 1], a10, a11, a12, a13, bh[2], bh[3]);
        }
    }

    // ---------------- RoPE in registers (both m-tiles) ----------------
#pragma unroll
    for (int nt = 0; nt < 8; nt++) {
        const int co = nt * 8 + 2 * u;
        {
            const float2 cA = *(const float2*)&C0[co];
            const float2 cB = *(const float2*)&C1[co];
            const float2 sA = *(const float2*)&S0[co];
            const float2 sB = *(const float2*)&S1[co];
            const float t0 = acc0[nt][0], t1 = acc0[nt][1];
            const float t2 = acc0[nt][2], t3 = acc0[nt][3];
            acc0[nt][0]     = t0 * cA.x - acc0[nt + 8][0] * sA.x;
            acc0[nt][1]     = t1 * cA.y - acc0[nt + 8][1] * sA.y;
            acc0[nt][2]     = t2 * cB.x - acc0[nt + 8][2] * sB.x;
            acc0[nt][3]     = t3 * cB.y - acc0[nt + 8][3] * sB.y;
            acc0[nt + 8][0] = acc0[nt + 8][0] * cA.x + t0 * sA.x;
            acc0[nt + 8][1] = acc0[nt + 8][1] * cA.y + t1 * sA.y;
            acc0[nt + 8][2] = acc0[nt + 8][2] * cB.x + t2 * sB.x;
            acc0[nt + 8][3] = acc0[nt + 8][3] * cB.y + t3 * sB.y;
        }
        {
            const float2 cA = *(const float2*)&C2[co];
            const float2 cB = *(const float2*)&C3[co];
            const float2 sA = *(const float2*)&S2[co];
            const float2 sB = *(const float2*)&S3[co];
            const float t0 = acc1[nt][0], t1 = acc1[nt][1];
            const float t2 = acc1[nt][2], t3 = acc1[nt][3];
            acc1[nt][0]     = t0 * cA.x - acc1[nt + 8][0] * sA.x;
            acc1[nt][1]     = t1 * cA.y - acc1[nt + 8][1] * sA.y;
            acc1[nt][2]     = t2 * cB.x - acc1[nt + 8][2] * sB.x;
            acc1[nt][3]     = t3 * cB.y - acc1[nt + 8][3] * sB.y;
            acc1[nt + 8][0] = acc1[nt + 8][0] * cA.x + t0 * sA.x;
            acc1[nt + 8][1] = acc1[nt + 8][1] * cA.y + t1 * sA.y;
            acc1[nt + 8][2] = acc1[nt + 8][2] * cB.x + t2 * sB.x;
            acc1[nt + 8][3] = acc1[nt + 8][3] * cB.y + t3 * sB.y;
        }
    }

    // pack z to fp16 A-fragments (acc dies -> frees regs)
    unsigned fh0[16][2], fh1[16][2];
#pragma unroll
    for (int n = 0; n < 16; n++) {
        fh0[n][0] = h2p(acc0[n][0], acc0[n][1]);
        fh0[n][1] = h2p(acc0[n][2], acc0[n][3]);
        fh1[n][0] = h2p(acc1[n][0], acc1[n][1]);
        fh1[n][1] = h2p(acc1[n][2], acc1[n][3]);
    }

    // ---------------- GEMM2: out = z @ Q (trans B) ----------------
    float o0[16][4], o1[16][4];
#pragma unroll
    for (int n = 0; n < 16; n++)
#pragma unroll
        for (int i = 0; i < 4; i++) { o0[n][i] = 0.f; o1[n][i] = 0.f; }

#pragma unroll
    for (int kt = 0; kt < 8; kt++) {
        const unsigned a00 = fh0[2 * kt][0],     a01 = fh0[2 * kt][1];
        const unsigned a02 = fh0[2 * kt + 1][0], a03 = fh0[2 * kt + 1][1];
        const unsigned a10 = fh1[2 * kt][0],     a11 = fh1[2 * kt][1];
        const unsigned a12 = fh1[2 * kt + 1][0], a13 = fh1[2 * kt + 1][1];
#pragma unroll
        for (int np = 0; np < 8; np++) {
            unsigned bh[4];
            ldsm4t(bh, su32(sQ + kt * 16 * QS + np * 16 + lbo));
            mma16816(o0[2 * np],     a00, a01, a02, a03, bh[0], bh[2]);
            mma16816(o0[2 * np + 1], a00, a01, a02, a03, bh[1], bh[3]);
            mma16816(o1[2 * np],     a10, a11, a12, a13, bh[0], bh[2]);
            mma16816(o1[2 * np + 1], a10, a11, a12, a13, bh[1], bh[3]);
        }
    }

    // ---------------- store ----------------
    float* O0 = out + (size_t)(base + warp * 32 + g) * 128;
    float* O1 = O0 + 8 * 128;
    float* O2 = O0 + 16 * 128;
    float* O3 = O0 + 24 * 128;
#pragma unroll
    for (int nt = 0; nt < 16; nt++) {
        const int col = nt * 8 + 2 * u;
        *(float2*)&O0[col] = make_float2(o0[nt][0], o0[nt][1]);
        *(float2*)&O1[col] = make_float2(o0[nt][2], o0[nt][3]);
        *(float2*)&O2[col] = make_float2(o1[nt][0], o1[nt][1]);
        *(float2*)&O3[col] = make_float2(o1[nt][2], o1[nt][3]);
    }
}

// ---------------------------------------------------------------------------
extern "C" void kernel_launch(void* const* d_in, const int* in_sizes, int n_in,
                              void* d_out, int out_size)
{
    (void)in_sizes; (void)n_in; (void)out_size;
    const float* q    = (const float*)d_in[0];
    const float* k    = (const float*)d_in[1];
    const float* vs   = (const float*)d_in[2];
    const float* cosg = (const float*)d_in[3];
    const float* sing = (const float*)d_in[4];
    float* out = (float*)d_out;

    build_p_kernel<<<32, 128>>>(vs);
    combine_q_kernel<<<128, 128>>>();
    rnrope_main<<<2048, 256>>>(q, k, cosg, sing, out);
}

// round 10
// speedup vs baseline: 1.0817x; 1.0817x over previous
#include <cuda_runtime.h>
#include <cuda_fp16.h>

#define NT  262144          /* B*H*S rows per tensor */
#define QS  136             /* smem row stride in halves */

__device__ __align__(16) float  g_P[2][16384];   /* partial Householder products */
__device__ __align__(16) __half g_Qhi[16384];    /* dm-permuted columns */

// ---------------------------------------------------------------------------
// Stage 1: two parallel 32-reflector partial products.
// ---------------------------------------------------------------------------
__global__ void build_p_kernel(const float* __restrict__ vs)
{
    __shared__ float svs[32 * 128];
    __shared__ float sinv[32];
    const int t = threadIdx.x;
    const int chunk = blockIdx.x >> 4;
    const float* vsrc = vs + chunk * 32 * 128;
    for (int i = t; i < 32 * 128; i += 128) svs[i] = vsrc[i];
    __syncthreads();
    if (t < 32) {
        float nn = 0.f;
#pragma unroll 8
        for (int i = 0; i < 128; i += 4) {
            const float4 v = *(const float4*)&svs[t * 128 + i];
            nn += v.x * v.x + v.y * v.y + v.z * v.z + v.w * v.w;
        }
        sinv[t] = 2.0f / (nn + 1e-8f);
    }
    __syncthreads();

    const int col = (blockIdx.x & 15) * 8 + (t >> 4);
    const int ip  = t & 15;
    float qc[8];
#pragma unroll
    for (int j = 0; j < 8; j++) qc[j] = (ip * 8 + j == col) ? 1.0f : 0.0f;

    for (int r = 0; r < 32; r++) {
        const float* v = &svs[r * 128 + ip * 8];
        float w = 0.f;
#pragma unroll
        for (int j = 0; j < 8; j++) w += v[j] * qc[j];
#pragma unroll
        for (int off = 8; off; off >>= 1) w += __shfl_xor_sync(0xffffffffu, w, off);
        const float sw = sinv[r] * w;
#pragma unroll
        for (int j = 0; j < 8; j++) qc[j] -= sw * v[j];
    }
#pragma unroll
    for (int j = 0; j < 8; j++) g_P[chunk][(ip * 8 + j) * 128 + col] = qc[j];
}

// ---------------------------------------------------------------------------
// Stage 2: Q = P2 * P1 (fp32) -> fp16, stored with dm-permuted columns:
// true col j goes to slot col m = (j&~15) | (hi<<3) | (u<<1) | k
// where u=(j&15)>>2, hi=(j>>1)&1, k=j&1.  (dm(m)=j)
// ---------------------------------------------------------------------------
__global__ void combine_q_kernel()
{
    __shared__ float row2[128];
    const int i = blockIdx.x, j = threadIdx.x;
    row2[j] = g_P[1][i * 128 + j];
    __syncthreads();
    float s = 0.f;
#pragma unroll 8
    for (int e = 0; e < 128; e++) s += row2[e] * g_P[0][e * 128 + j];
    const int u  = (j & 15) >> 2;
    const int hi = (j >> 1) & 1;
    const int k  = j & 1;
    const int m  = (j & ~15) | (hi << 3) | (u << 1) | k;
    g_Qhi[i * 128 + m] = __float2half_rn(s);
}

// ---------------------------------------------------------------------------
__device__ __forceinline__ unsigned su32(const void* p)
{
    return (unsigned)__cvta_generic_to_shared(p);
}
__device__ __forceinline__ void ldsm4(unsigned r[4], unsigned a)
{
    asm volatile("ldmatrix.sync.aligned.m8n8.x4.shared.b16 {%0,%1,%2,%3}, [%4];\n"
                 : "=r"(r[0]), "=r"(r[1]), "=r"(r[2]), "=r"(r[3]) : "r"(a));
}
__device__ __forceinline__ void ldsm4t(unsigned r[4], unsigned a)
{
    asm volatile("ldmatrix.sync.aligned.m8n8.x4.trans.shared.b16 {%0,%1,%2,%3}, [%4];\n"
                 : "=r"(r[0]), "=r"(r[1]), "=r"(r[2]), "=r"(r[3]) : "r"(a));
}
__device__ __forceinline__ void mma16816(float c[4],
    unsigned a0, unsigned a1, unsigned a2, unsigned a3, unsigned b0, unsigned b1)
{
    asm volatile("mma.sync.aligned.m16n8k16.row.col.f32.f16.f16.f32 "
                 "{%0,%1,%2,%3}, {%4,%5,%6,%7}, {%8,%9}, {%0,%1,%2,%3};\n"
                 : "+f"(c[0]), "+f"(c[1]), "+f"(c[2]), "+f"(c[3])
                 : "r"(a0), "r"(a1), "r"(a2), "r"(a3), "r"(b0), "r"(b1));
}
__device__ __forceinline__ unsigned h2p(float a, float b)
{
    __half2 h = __floats2half2_rn(a, b);
    return *reinterpret_cast<unsigned*>(&h);
}

// ---------------------------------------------------------------------------
// Main kernel: 256 rows/CTA, 8 warps x 32 rows, single-pass fp16.
// dm-permuted k-slots: A-loads and stores are contiguous float4 per thread.
// GEMM1 (x@Q^T) -> RoPE in regs -> pack fp16 -> GEMM2 (z@Q, trans B) -> store.
// ---------------------------------------------------------------------------
__global__ __launch_bounds__(256)
void rnrope_main(const float* __restrict__ qg, const float* __restrict__ kg,
                 const float* __restrict__ cosg, const float* __restrict__ sing,
                 float* __restrict__ out)
{
    __shared__ __align__(16) __half sQ[128 * QS];    /* 34816 B */

    const int tid = threadIdx.x;
    for (int i = tid; i < 128 * 16; i += 256) {
        const int row = i >> 4;
        const int ch  = (i & 15) * 8;
        *(uint4*)&sQ[row * QS + ch] = *(const uint4*)&g_Qhi[row * 128 + ch];
    }
    __syncthreads();

    const int warp = tid >> 5, lane = tid & 31;
    const int u = lane & 3, g = lane >> 2;

    const int base  = blockIdx.x * 256;                /* 2048 blocks */
    const int local = (base < NT) ? base : base - NT;
    const float* x  = (base < NT) ? qg : kg;

    const float* A0 = x + (size_t)(local + warp * 32 + g) * 128;
    const float* A1 = A0 + 8 * 128;
    const float* A2 = A0 + 16 * 128;
    const float* A3 = A0 + 24 * 128;

    const int csr = ((local >> 17) << 13) + (local & 8191) + warp * 32 + g;
    const float* C0  = cosg + (size_t)csr * 128;
    const float* C1  = C0 + 8 * 128;
    const float* C2  = C0 + 16 * 128;
    const float* C3  = C0 + 24 * 128;
    const float* S0  = sing + (size_t)csr * 128;
    const float* S1  = S0 + 8 * 128;
    const float* S2  = S0 + 16 * 128;
    const float* S3  = S0 + 24 * 128;

    const int lbo = (((lane >> 4) << 3) + (lane & 7)) * QS + (((lane >> 3) & 1) << 3);

    float acc0[16][4], acc1[16][4];
#pragma unroll
    for (int n = 0; n < 16; n++)
#pragma unroll
        for (int i = 0; i < 4; i++) { acc0[n][i] = 0.f; acc1[n][i] = 0.f; }

    // ------- GEMM1: y = x @ Q^T (A via contiguous float4, dm slots) -------
#pragma unroll
    for (int kt = 0; kt < 8; kt++) {
        const int co = kt * 16 + 4 * u;
        const float4 r0 = *(const float4*)&A0[co];
        const float4 r1 = *(const float4*)&A1[co];
        const float4 r2 = *(const float4*)&A2[co];
        const float4 r3 = *(const float4*)&A3[co];
        const unsigned a00 = h2p(r0.x, r0.y), a01 = h2p(r1.x, r1.y);
        const unsigned a02 = h2p(r0.z, r0.w), a03 = h2p(r1.z, r1.w);
        const unsigned a10 = h2p(r2.x, r2.y), a11 = h2p(r3.x, r3.y);
        const unsigned a12 = h2p(r2.z, r2.w), a13 = h2p(r3.z, r3.w);
#pragma unroll
        for (int np = 0; np < 8; np++) {
            unsigned bh[4];
            ldsm4(bh, su32(sQ + np * (16 * QS) + kt * 16 + lbo));
            mma16816(acc0[2 * np],     a00, a01, a02, a03, bh[0], bh[1]);
            mma16816(acc0[2 * np + 1], a00, a01, a02, a03, bh[2], bh[3]);
            mma16816(acc1[2 * np],     a10, a11, a12, a13, bh[0], bh[1]);
            mma16816(acc1[2 * np + 1], a10, a11, a12, a13, bh[2], bh[3]);
        }
    }

    // ---------------- RoPE in registers (n-dim unpermuted) ----------------
#pragma unroll
    for (int nt = 0; nt < 8; nt++) {
        const int co = nt * 8 + 2 * u;
        {
            const float2 cA = *(const float2*)&C0[co];
            const float2 cB = *(const float2*)&C1[co];
            const float2 sA = *(const float2*)&S0[co];
            const float2 sB = *(const float2*)&S1[co];
            const float t0 = acc0[nt][0], t1 = acc0[nt][1];
            const float t2 = acc0[nt][2], t3 = acc0[nt][3];
            acc0[nt][0]     = t0 * cA.x - acc0[nt + 8][0] * sA.x;
            acc0[nt][1]     = t1 * cA.y - acc0[nt + 8][1] * sA.y;
            acc0[nt][2]     = t2 * cB.x - acc0[nt + 8][2] * sB.x;
            acc0[nt][3]     = t3 * cB.y - acc0[nt + 8][3] * sB.y;
            acc0[nt + 8][0] = acc0[nt + 8][0] * cA.x + t0 * sA.x;
            acc0[nt + 8][1] = acc0[nt + 8][1] * cA.y + t1 * sA.y;
            acc0[nt + 8][2] = acc0[nt + 8][2] * cB.x + t2 * sB.x;
            acc0[nt + 8][3] = acc0[nt + 8][3] * cB.y + t3 * sB.y;
        }
        {
            const float2 cA = *(const float2*)&C2[co];
            const float2 cB = *(const float2*)&C3[co];
            const float2 sA = *(const float2*)&S2[co];
            const float2 sB = *(const float2*)&S3[co];
            const float t0 = acc1[nt][0], t1 = acc1[nt][1];
            const float t2 = acc1[nt][2], t3 = acc1[nt][3];
            acc1[nt][0]     = t0 * cA.x - acc1[nt + 8][0] * sA.x;
            acc1[nt][1]     = t1 * cA.y - acc1[nt + 8][1] * sA.y;
            acc1[nt][2]     = t2 * cB.x - acc1[nt + 8][2] * sB.x;
            acc1[nt][3]     = t3 * cB.y - acc1[nt + 8][3] * sB.y;
            acc1[nt + 8][0] = acc1[nt + 8][0] * cA.x + t0 * sA.x;
            acc1[nt + 8][1] = acc1[nt + 8][1] * cA.y + t1 * sA.y;
            acc1[nt + 8][2] = acc1[nt + 8][2] * cB.x + t2 * sB.x;
            acc1[nt + 8][3] = acc1[nt + 8][3] * cB.y + t3 * sB.y;
        }
    }

    // pack z to fp16 A-fragments
    unsigned fh0[16][2], fh1[16][2];
#pragma unroll
    for (int n = 0; n < 16; n++) {
        fh0[n][0] = h2p(acc0[n][0], acc0[n][1]);
        fh0[n][1] = h2p(acc0[n][2], acc0[n][3]);
        fh1[n][0] = h2p(acc1[n][0], acc1[n][1]);
        fh1[n][1] = h2p(acc1[n][2], acc1[n][3]);
    }

    // ---------------- GEMM2: out = z @ Q (trans B) ----------------
    float o0[16][4], o1[16][4];
#pragma unroll
    for (int n = 0; n < 16; n++)
#pragma unroll
        for (int i = 0; i < 4; i++) { o0[n][i] = 0.f; o1[n][i] = 0.f; }

#pragma unroll
    for (int kt = 0; kt < 8; kt++) {
        const unsigned a00 = fh0[2 * kt][0],     a01 = fh0[2 * kt][1];
        const unsigned a02 = fh0[2 * kt + 1][0], a03 = fh0[2 * kt + 1][1];
        const unsigned a10 = fh1[2 * kt][0],     a11 = fh1[2 * kt][1];
        const unsigned a12 = fh1[2 * kt + 1][0], a13 = fh1[2 * kt + 1][1];
#pragma unroll
        for (int np = 0; np < 8; np++) {
            unsigned bh[4];
            ldsm4t(bh, su32(sQ + kt * 16 * QS + np * 16 + lbo));
            mma16816(o0[2 * np],     a00, a01, a02, a03, bh[0], bh[2]);
            mma16816(o0[2 * np + 1], a00, a01, a02, a03, bh[1], bh[3]);
            mma16816(o1[2 * np],     a10, a11, a12, a13, bh[0], bh[2]);
            mma16816(o1[2 * np + 1], a10, a11, a12, a13, bh[1], bh[3]);
        }
    }

    // ------- store: slot col m=8j+2u+k -> true col 16np+4u+2j+k = float4 ---
    float* O0 = out + (size_t)(base + warp * 32 + g) * 128;
    float* O1 = O0 + 8 * 128;
    float* O2 = O0 + 16 * 128;
    float* O3 = O0 + 24 * 128;
#pragma unroll
    for (int np = 0; np < 8; np++) {
        const int col = np * 16 + 4 * u;
        *(float4*)&O0[col] = make_float4(o0[2*np][0], o0[2*np][1], o0[2*np+1][0], o0[2*np+1][1]);
        *(float4*)&O1[col] = make_float4(o0[2*np][2], o0[2*np][3], o0[2*np+1][2], o0[2*np+1][3]);
        *(float4*)&O2[col] = make_float4(o1[2*np][0], o1[2*np][1], o1[2*np+1][0], o1[2*np+1][1]);
        *(float4*)&O3[col] = make_float4(o1[2*np][2], o1[2*np][3], o1[2*np+1][2], o1[2*np+1][3]);
    }
}

// ---------------------------------------------------------------------------
extern "C" void kernel_launch(void* const* d_in, const int* in_sizes, int n_in,
                              void* d_out, int out_size)
{
    (void)in_sizes; (void)n_in; (void)out_size;
    const float* q    = (const float*)d_in[0];
    const float* k    = (const float*)d_in[1];
    const float* vs   = (const float*)d_in[2];
    const float* cosg = (const float*)d_in[3];
    const float* sing = (const float*)d_in[4];
    float* out = (float*)d_out;

    build_p_kernel<<<32, 128>>>(vs);
    combine_q_kernel<<<128, 128>>>();
    rnrope_main<<<2048, 256>>>(q, k, cosg, sing, out);
}

// round 11
// speedup vs baseline: 1.1131x; 1.0290x over previous
#include <cuda_runtime.h>
#include <cuda_fp16.h>

#define NT  262144          /* B*H*S rows per tensor */
#define QS  136             /* smem row stride in halves */

__device__ __align__(16) float  g_P[4][16384];   /* 16-reflector partial products */
__device__ __align__(16) float  g_L[2][16384];   /* level-1 combines */
__device__ __align__(16) __half g_Qhi[16384];    /* em/dm-permuted Q */

// ---------------------------------------------------------------------------
// Stage 1: four parallel 16-reflector partial products.
// C_c = H_{c*16+16} ... H_{c*16+1}.  grid 64 x 128: chunk = bid>>4.
// ---------------------------------------------------------------------------
__global__ void build_p_kernel(const float* __restrict__ vs)
{
    __shared__ float svs[16 * 128];
    __shared__ float sinv[16];
    const int t = threadIdx.x;
    const int chunk = blockIdx.x >> 4;
    const float* vsrc = vs + chunk * 16 * 128;
    for (int i = t; i < 16 * 128; i += 128) svs[i] = vsrc[i];
    __syncthreads();
    if (t < 16) {
        float nn = 0.f;
#pragma unroll 8
        for (int i = 0; i < 128; i += 4) {
            const float4 v = *(const float4*)&svs[t * 128 + i];
            nn += v.x * v.x + v.y * v.y + v.z * v.z + v.w * v.w;
        }
        sinv[t] = 2.0f / (nn + 1e-8f);
    }
    __syncthreads();

    const int col = (blockIdx.x & 15) * 8 + (t >> 4);
    const int ip  = t & 15;
    float qc[8];
#pragma unroll
    for (int j = 0; j < 8; j++) qc[j] = (ip * 8 + j == col) ? 1.0f : 0.0f;

    for (int r = 0; r < 16; r++) {
        const float* v = &svs[r * 128 + ip * 8];
        float w = 0.f;
#pragma unroll
        for (int j = 0; j < 8; j++) w += v[j] * qc[j];
#pragma unroll
        for (int off = 8; off; off >>= 1) w += __shfl_xor_sync(0xffffffffu, w, off);
        const float sw = sinv[r] * w;
#pragma unroll
        for (int j = 0; j < 8; j++) qc[j] -= sw * v[j];
    }
#pragma unroll
    for (int j = 0; j < 8; j++) g_P[chunk][(ip * 8 + j) * 128 + col] = qc[j];
}

// ---------------------------------------------------------------------------
// Stage 2a: level-1 combine.  grid 256: lvl = bid>>7 (0: C2*C1, 1: C4*C3).
// ---------------------------------------------------------------------------
__global__ void combine1_kernel()
{
    __shared__ float rowa[128];
    const int lvl = blockIdx.x >> 7;
    const int i = blockIdx.x & 127, j = threadIdx.x;
    rowa[j] = g_P[2 * lvl + 1][i * 128 + j];
    __syncthreads();
    float s = 0.f;
#pragma unroll 8
    for (int e = 0; e < 128; e++) s += rowa[e] * g_P[2 * lvl][e * 128 + j];
    g_L[lvl][i * 128 + j] = s;
}

// ---------------------------------------------------------------------------
// Stage 2b: Q = L1 * L0 -> fp16, both dims permuted:
// true index j -> slot p(j) = (j&~15) | (((j>>1)&1)<<3) | (((j&15)>>2)<<1) | (j&1)
// (rows: em == same formula; cols: dm).
// ---------------------------------------------------------------------------
__global__ void combine2_kernel()
{
    __shared__ float rowa[128];
    const int i = blockIdx.x, j = threadIdx.x;
    rowa[j] = g_L[1][i * 128 + j];
    __syncthreads();
    float s = 0.f;
#pragma unroll 8
    for (int e = 0; e < 128; e++) s += rowa[e] * g_L[0][e * 128 + j];
    const int mi = (i & ~15) | (((i >> 1) & 1) << 3) | (((i & 15) >> 2) << 1) | (i & 1);
    const int mj = (j & ~15) | (((j >> 1) & 1) << 3) | (((j & 15) >> 2) << 1) | (j & 1);
    g_Qhi[mi * 128 + mj] = __float2half_rn(s);
}

// ---------------------------------------------------------------------------
__device__ __forceinline__ unsigned su32(const void* p)
{
    return (unsigned)__cvta_generic_to_shared(p);
}
__device__ __forceinline__ void ldsm4(unsigned r[4], unsigned a)
{
    asm volatile("ldmatrix.sync.aligned.m8n8.x4.shared.b16 {%0,%1,%2,%3}, [%4];\n"
                 : "=r"(r[0]), "=r"(r[1]), "=r"(r[2]), "=r"(r[3]) : "r"(a));
}
__device__ __forceinline__ void ldsm4t(unsigned r[4], unsigned a)
{
    asm volatile("ldmatrix.sync.aligned.m8n8.x4.trans.shared.b16 {%0,%1,%2,%3}, [%4];\n"
                 : "=r"(r[0]), "=r"(r[1]), "=r"(r[2]), "=r"(r[3]) : "r"(a));
}
__device__ __forceinline__ void mma16816(float c[4],
    unsigned a0, unsigned a1, unsigned a2, unsigned a3, unsigned b0, unsigned b1)
{
    asm volatile("mma.sync.aligned.m16n8k16.row.col.f32.f16.f16.f32 "
                 "{%0,%1,%2,%3}, {%4,%5,%6,%7}, {%8,%9}, {%0,%1,%2,%3};\n"
                 : "+f"(c[0]), "+f"(c[1]), "+f"(c[2]), "+f"(c[3])
                 : "r"(a0), "r"(a1), "r"(a2), "r"(a3), "r"(b0), "r"(b1));
}
__device__ __forceinline__ unsigned h2p(float a, float b)
{
    __half2 h = __floats2half2_rn(a, b);
    return *reinterpret_cast<unsigned*>(&h);
}

// ---------------------------------------------------------------------------
// Main kernel: 256 rows/CTA, 8 warps x 32 rows, single-pass fp16.
// Both mma free axes permuted -> A-loads, cos/sin loads, and stores are all
// contiguous float4 per thread.
// ---------------------------------------------------------------------------
__global__ __launch_bounds__(256)
void rnrope_main(const float* __restrict__ qg, const float* __restrict__ kg,
                 const float* __restrict__ cosg, const float* __restrict__ sing,
                 float* __restrict__ out)
{
    __shared__ __align__(16) __half sQ[128 * QS];    /* 34816 B */

    const int tid = threadIdx.x;
    for (int i = tid; i < 128 * 16; i += 256) {
        const int row = i >> 4;
        const int ch  = (i & 15) * 8;
        *(uint4*)&sQ[row * QS + ch] = *(const uint4*)&g_Qhi[row * 128 + ch];
    }
    __syncthreads();

    const int warp = tid >> 5, lane = tid & 31;
    const int u = lane & 3, g = lane >> 2;

    const int base  = blockIdx.x * 256;                /* 2048 blocks */
    const int local = (base < NT) ? base : base - NT;
    const float* x  = (base < NT) ? qg : kg;

    const float* A0 = x + (size_t)(local + warp * 32 + g) * 128;
    const float* A1 = A0 + 8 * 128;
    const float* A2 = A0 + 16 * 128;
    const float* A3 = A0 + 24 * 128;

    const int csr = ((local >> 17) << 13) + (local & 8191) + warp * 32 + g;
    const float* C0  = cosg + (size_t)csr * 128;
    const float* C1  = C0 + 8 * 128;
    const float* C2  = C0 + 16 * 128;
    const float* C3  = C0 + 24 * 128;
    const float* S0  = sing + (size_t)csr * 128;
    const float* S1  = S0 + 8 * 128;
    const float* S2  = S0 + 16 * 128;
    const float* S3  = S0 + 24 * 128;

    const int lbo = (((lane >> 4) << 3) + (lane & 7)) * QS + (((lane >> 3) & 1) << 3);

    float acc0[16][4], acc1[16][4];
#pragma unroll
    for (int n = 0; n < 16; n++)
#pragma unroll
        for (int i = 0; i < 4; i++) { acc0[n][i] = 0.f; acc1[n][i] = 0.f; }

    // ------- GEMM1: y = x @ Q^T (A via contiguous float4, dm slots) -------
#pragma unroll
    for (int kt = 0; kt < 8; kt++) {
        const int co = kt * 16 + 4 * u;
        const float4 r0 = *(const float4*)&A0[co];
        const float4 r1 = *(const float4*)&A1[co];
        const float4 r2 = *(const float4*)&A2[co];
        const float4 r3 = *(const float4*)&A3[co];
        const unsigned a00 = h2p(r0.x, r0.y), a01 = h2p(r1.x, r1.y);
        const unsigned a02 = h2p(r0.z, r0.w), a03 = h2p(r1.z, r1.w);
        const unsigned a10 = h2p(r2.x, r2.y), a11 = h2p(r3.x, r3.y);
        const unsigned a12 = h2p(r2.z, r2.w), a13 = h2p(r3.z, r3.w);
#pragma unroll
        for (int np = 0; np < 8; np++) {
            unsigned bh[4];
            ldsm4(bh, su32(sQ + np * (16 * QS) + kt * 16 + lbo));
            mma16816(acc0[2 * np],     a00, a01, a02, a03, bh[0], bh[1]);
            mma16816(acc0[2 * np + 1], a00, a01, a02, a03, bh[2], bh[3]);
            mma16816(acc1[2 * np],     a10, a11, a12, a13, bh[0], bh[1]);
            mma16816(acc1[2 * np + 1], a10, a11, a12, a13, bh[2], bh[3]);
        }
    }

    // ---- RoPE in registers; e-axis em-permuted -> float4 cos/sin loads ----
    // acc[2np+j][i]: true e col = 16np + 4u + 2j + (i&1), row g + 8*(i>>1).
    // partner tile np+4 holds true cols +64 (same cos/sin values).
#pragma unroll
    for (int np = 0; np < 4; np++) {
        const int co = np * 16 + 4 * u;
        const float4 cg  = *(const float4*)&C0[co];
        const float4 cg8 = *(const float4*)&C1[co];
        const float4 sg  = *(const float4*)&S0[co];
        const float4 sg8 = *(const float4*)&S1[co];
        const float4 dg  = *(const float4*)&C2[co];
        const float4 dg8 = *(const float4*)&C3[co];
        const float4 tg  = *(const float4*)&S2[co];
        const float4 tg8 = *(const float4*)&S3[co];
#pragma unroll
        for (int j = 0; j < 2; j++) {
            const int n0 = 2 * np + j, n1 = n0 + 8;
            const float c0v = j ? cg.z  : cg.x,  c1v = j ? cg.w  : cg.y;
            const float c2v = j ? cg8.z : cg8.x, c3v = j ? cg8.w : cg8.y;
            const float s0v = j ? sg.z  : sg.x,  s1v = j ? sg.w  : sg.y;
            const float s2v = j ? sg8.z : sg8.x, s3v = j ? sg8.w : sg8.y;
            {
                const float t0 = acc0[n0][0], t1 = acc0[n0][1];
                const float t2 = acc0[n0][2], t3 = acc0[n0][3];
                acc0[n0][0] = t0 * c0v - acc0[n1][0] * s0v;
                acc0[n0][1] = t1 * c1v - acc0[n1][1] * s1v;
                acc0[n0][2] = t2 * c2v - acc0[n1][2] * s2v;
                acc0[n0][3] = t3 * c3v - acc0[n1][3] * s3v;
                acc0[n1][0] = acc0[n1][0] * c0v + t0 * s0v;
                acc0[n1][1] = acc0[n1][1] * c1v + t1 * s1v;
                acc0[n1][2] = acc0[n1][2] * c2v + t2 * s2v;
                acc0[n1][3] = acc0[n1][3] * c3v + t3 * s3v;
            }
            const float d0v = j ? dg.z  : dg.x,  d1v = j ? dg.w  : dg.y;
            const float d2v = j ? dg8.z : dg8.x, d3v = j ? dg8.w : dg8.y;
            const float t0v = j ? tg.z  : tg.x,  t1v = j ? tg.w  : tg.y;
            const float t2v = j ? tg8.z : tg8.x, t3v = j ? tg8.w : tg8.y;
            {
                const float t0 = acc1[n0][0], t1 = acc1[n0][1];
                const float t2 = acc1[n0][2], t3 = acc1[n0][3];
                acc1[n0][0] = t0 * d0v - acc1[n1][0] * t0v;
                acc1[n0][1] = t1 * d1v - acc1[n1][1] * t1v;
                acc1[n0][2] = t2 * d2v - acc1[n1][2] * t2v;
                acc1[n0][3] = t3 * d3v - acc1[n1][3] * t3v;
                acc1[n1][0] = acc1[n1][0] * d0v + t0 * t0v;
                acc1[n1][1] = acc1[n1][1] * d1v + t1 * t1v;
                acc1[n1][2] = acc1[n1][2] * d2v + t2 * t2v;
                acc1[n1][3] = acc1[n1][3] * d3v + t3 * t3v;
            }
        }
    }

    // pack z to fp16 A-fragments
    unsigned fh0[16][2], fh1[16][2];
#pragma unroll
    for (int n = 0; n < 16; n++) {
        fh0[n][0] = h2p(acc0[n][0], acc0[n][1]);
        fh0[n][1] = h2p(acc0[n][2], acc0[n][3]);
        fh1[n][0] = h2p(acc1[n][0], acc1[n][1]);
        fh1[n][1] = h2p(acc1[n][2], acc1[n][3]);
    }

    // ---------------- GEMM2: out = z @ Q (trans B) ----------------
    float o0[16][4], o1[16][4];
#pragma unroll
    for (int n = 0; n < 16; n++)
#pragma unroll
        for (int i = 0; i < 4; i++) { o0[n][i] = 0.f; o1[n][i] = 0.f; }

#pragma unroll
    for (int kt = 0; kt < 8; kt++) {
        const unsigned a00 = fh0[2 * kt][0],     a01 = fh0[2 * kt][1];
        const unsigned a02 = fh0[2 * kt + 1][0], a03 = fh0[2 * kt + 1][1];
        const unsigned a10 = fh1[2 * kt][0],     a11 = fh1[2 * kt][1];
        const unsigned a12 = fh1[2 * kt + 1][0], a13 = fh1[2 * kt + 1][1];
#pragma unroll
        for (int np = 0; np < 8; np++) {
            unsigned bh[4];
            ldsm4t(bh, su32(sQ + kt * 16 * QS + np * 16 + lbo));
            mma16816(o0[2 * np],     a00, a01, a02, a03, bh[0], bh[2]);
            mma16816(o0[2 * np + 1], a00, a01, a02, a03, bh[1], bh[3]);
            mma16816(o1[2 * np],     a10, a11, a12, a13, bh[0], bh[2]);
            mma16816(o1[2 * np + 1], a10, a11, a12, a13, bh[1], bh[3]);
        }
    }

    // ------- store: slot col -> true col 16np+4u+2j+k = contiguous float4 --
    float* O0 = out + (size_t)(base + warp * 32 + g) * 128;
    float* O1 = O0 + 8 * 128;
    float* O2 = O0 + 16 * 128;
    float* O3 = O0 + 24 * 128;
#pragma unroll
    for (int np = 0; np < 8; np++) {
        const int col = np * 16 + 4 * u;
        *(float4*)&O0[col] = make_float4(o0[2*np][0], o0[2*np][1], o0[2*np+1][0], o0[2*np+1][1]);
        *(float4*)&O1[col] = make_float4(o0[2*np][2], o0[2*np][3], o0[2*np+1][2], o0[2*np+1][3]);
        *(float4*)&O2[col] = make_float4(o1[2*np][0], o1[2*np][1], o1[2*np+1][0], o1[2*np+1][1]);
        *(float4*)&O3[col] = make_float4(o1[2*np][2], o1[2*np][3], o1[2*np+1][2], o1[2*np+1][3]);
    }
}

// ---------------------------------------------------------------------------
extern "C" void kernel_launch(void* const* d_in, const int* in_sizes, int n_in,
                              void* d_out, int out_size)
{
    (void)in_sizes; (void)n_in; (void)out_size;
    const float* q    = (const float*)d_in[0];
    const float* k    = (const float*)d_in[1];
    const float* vs   = (const float*)d_in[2];
    const float* cosg = (const float*)d_in[3];
    const float* sing = (const float*)d_in[4];
    float* out = (float*)d_out;

    build_p_kernel<<<64, 128>>>(vs);
    combine1_kernel<<<256, 128>>>();
    combine2_kernel<<<128, 128>>>();
    rnrope_main<<<2048, 256>>>(q, k, cosg, sing, out);
}

// round 12
// speedup vs baseline: 1.1794x; 1.0596x over previous
#include <cuda_runtime.h>
#include <cuda_fp16.h>

#define NT  262144          /* B*H*S rows per tensor */
#define QS  136             /* smem row stride in halves */

__device__ __align__(16) float  g_P[4][16384];   /* 16-reflector partial products */
__device__ __align__(16) float  g_L[2][16384];   /* level-1 combines */
__device__ __align__(16) __half g_Qhi[16384];    /* em/dm-permuted Q */

// ---------------------------------------------------------------------------
// Stage 1: four parallel 16-reflector partial products.
// ---------------------------------------------------------------------------
__global__ void build_p_kernel(const float* __restrict__ vs)
{
    __shared__ float svs[16 * 128];
    __shared__ float sinv[16];
    const int t = threadIdx.x;
    const int chunk = blockIdx.x >> 4;
    const float* vsrc = vs + chunk * 16 * 128;
    for (int i = t; i < 16 * 128; i += 128) svs[i] = vsrc[i];
    __syncthreads();
    if (t < 16) {
        float nn = 0.f;
#pragma unroll 8
        for (int i = 0; i < 128; i += 4) {
            const float4 v = *(const float4*)&svs[t * 128 + i];
            nn += v.x * v.x + v.y * v.y + v.z * v.z + v.w * v.w;
        }
        sinv[t] = 2.0f / (nn + 1e-8f);
    }
    __syncthreads();

    const int col = (blockIdx.x & 15) * 8 + (t >> 4);
    const int ip  = t & 15;
    float qc[8];
#pragma unroll
    for (int j = 0; j < 8; j++) qc[j] = (ip * 8 + j == col) ? 1.0f : 0.0f;

    for (int r = 0; r < 16; r++) {
        const float* v = &svs[r * 128 + ip * 8];
        float w = 0.f;
#pragma unroll
        for (int j = 0; j < 8; j++) w += v[j] * qc[j];
#pragma unroll
        for (int off = 8; off; off >>= 1) w += __shfl_xor_sync(0xffffffffu, w, off);
        const float sw = sinv[r] * w;
#pragma unroll
        for (int j = 0; j < 8; j++) qc[j] -= sw * v[j];
    }
#pragma unroll
    for (int j = 0; j < 8; j++) g_P[chunk][(ip * 8 + j) * 128 + col] = qc[j];
}

// ---------------------------------------------------------------------------
// Stage 2a: level-1 combine.
// ---------------------------------------------------------------------------
__global__ void combine1_kernel()
{
    __shared__ float rowa[128];
    const int lvl = blockIdx.x >> 7;
    const int i = blockIdx.x & 127, j = threadIdx.x;
    rowa[j] = g_P[2 * lvl + 1][i * 128 + j];
    __syncthreads();
    float s = 0.f;
#pragma unroll 8
    for (int e = 0; e < 128; e++) s += rowa[e] * g_P[2 * lvl][e * 128 + j];
    g_L[lvl][i * 128 + j] = s;
}

// ---------------------------------------------------------------------------
// Stage 2b: Q = L1 * L0 -> fp16, both dims within-16 permuted.
// ---------------------------------------------------------------------------
__global__ void combine2_kernel()
{
    __shared__ float rowa[128];
    const int i = blockIdx.x, j = threadIdx.x;
    rowa[j] = g_L[1][i * 128 + j];
    __syncthreads();
    float s = 0.f;
#pragma unroll 8
    for (int e = 0; e < 128; e++) s += rowa[e] * g_L[0][e * 128 + j];
    const int mi = (i & ~15) | (((i >> 1) & 1) << 3) | (((i & 15) >> 2) << 1) | (i & 1);
    const int mj = (j & ~15) | (((j >> 1) & 1) << 3) | (((j & 15) >> 2) << 1) | (j & 1);
    g_Qhi[mi * 128 + mj] = __float2half_rn(s);
}

// ---------------------------------------------------------------------------
__device__ __forceinline__ unsigned su32(const void* p)
{
    return (unsigned)__cvta_generic_to_shared(p);
}
__device__ __forceinline__ void ldsm4(unsigned r[4], unsigned a)
{
    asm volatile("ldmatrix.sync.aligned.m8n8.x4.shared.b16 {%0,%1,%2,%3}, [%4];\n"
                 : "=r"(r[0]), "=r"(r[1]), "=r"(r[2]), "=r"(r[3]) : "r"(a));
}
__device__ __forceinline__ void ldsm4t(unsigned r[4], unsigned a)
{
    asm volatile("ldmatrix.sync.aligned.m8n8.x4.trans.shared.b16 {%0,%1,%2,%3}, [%4];\n"
                 : "=r"(r[0]), "=r"(r[1]), "=r"(r[2]), "=r"(r[3]) : "r"(a));
}
__device__ __forceinline__ void mma16816(float c[4],
    unsigned a0, unsigned a1, unsigned a2, unsigned a3, unsigned b0, unsigned b1)
{
    asm volatile("mma.sync.aligned.m16n8k16.row.col.f32.f16.f16.f32 "
                 "{%0,%1,%2,%3}, {%4,%5,%6,%7}, {%8,%9}, {%0,%1,%2,%3};\n"
                 : "+f"(c[0]), "+f"(c[1]), "+f"(c[2]), "+f"(c[3])
                 : "r"(a0), "r"(a1), "r"(a2), "r"(a3), "r"(b0), "r"(b1));
}
__device__ __forceinline__ unsigned h2p(float a, float b)
{
    __half2 h = __floats2half2_rn(a, b);
    return *reinterpret_cast<unsigned*>(&h);
}

// ---------------------------------------------------------------------------
// Main kernel: 128 rows/CTA, 8 warps x 16 rows, single-pass fp16, 2 CTAs/SM.
// Both mma free axes permuted -> A-loads, cos/sin loads, stores all float4.
// ---------------------------------------------------------------------------
__global__ __launch_bounds__(256, 2)
void rnrope_main(const float* __restrict__ qg, const float* __restrict__ kg,
                 const float* __restrict__ cosg, const float* __restrict__ sing,
                 float* __restrict__ out)
{
    __shared__ __align__(16) __half sQ[128 * QS];    /* 34816 B */

    const int tid = threadIdx.x;
    for (int i = tid; i < 128 * 16; i += 256) {
        const int row = i >> 4;
        const int ch  = (i & 15) * 8;
        *(uint4*)&sQ[row * QS + ch] = *(const uint4*)&g_Qhi[row * 128 + ch];
    }
    __syncthreads();

    const int warp = tid >> 5, lane = tid & 31;
    const int u = lane & 3, g = lane >> 2;

    const int base  = blockIdx.x * 128;                /* 4096 blocks */
    const int local = (base < NT) ? base : base - NT;
    const float* x  = (base < NT) ? qg : kg;

    const float* A0 = x + (size_t)(local + warp * 16 + g) * 128;
    const float* A1 = A0 + 8 * 128;

    const int csr = ((local >> 17) << 13) + (local & 8191) + warp * 16 + g;
    const float* C0 = cosg + (size_t)csr * 128;
    const float* C1 = C0 + 8 * 128;
    const float* S0 = sing + (size_t)csr * 128;
    const float* S1 = S0 + 8 * 128;

    const int lbo = (((lane >> 4) << 3) + (lane & 7)) * QS + (((lane >> 3) & 1) << 3);

    float acc[16][4];
#pragma unroll
    for (int n = 0; n < 16; n++)
#pragma unroll
        for (int i = 0; i < 4; i++) acc[n][i] = 0.f;

    // ------- GEMM1: y = x @ Q^T (A via contiguous float4, dm slots) -------
#pragma unroll
    for (int kt = 0; kt < 8; kt++) {
        const int co = kt * 16 + 4 * u;
        const float4 r0 = *(const float4*)&A0[co];
        const float4 r1 = *(const float4*)&A1[co];
        const unsigned a0 = h2p(r0.x, r0.y), a1 = h2p(r1.x, r1.y);
        const unsigned a2 = h2p(r0.z, r0.w), a3 = h2p(r1.z, r1.w);
#pragma unroll
        for (int np = 0; np < 8; np++) {
            unsigned bh[4];
            ldsm4(bh, su32(sQ + np * (16 * QS) + kt * 16 + lbo));
            mma16816(acc[2 * np],     a0, a1, a2, a3, bh[0], bh[1]);
            mma16816(acc[2 * np + 1], a0, a1, a2, a3, bh[2], bh[3]);
        }
    }

    // ---- RoPE in registers; e-axis em-permuted -> float4 cos/sin loads ----
    // acc[2np+j][i]: true e col = 16np + 4u + 2j + (i&1); rows g / g+8.
    // partner tile np+4 holds true cols +64 (same cos/sin values).
#pragma unroll
    for (int np = 0; np < 4; np++) {
        const int co = np * 16 + 4 * u;
        const float4 cg  = *(const float4*)&C0[co];
        const float4 cg8 = *(const float4*)&C1[co];
        const float4 sg  = *(const float4*)&S0[co];
        const float4 sg8 = *(const float4*)&S1[co];
#pragma unroll
        for (int j = 0; j < 2; j++) {
            const int n0 = 2 * np + j, n1 = n0 + 8;
            const float c0v = j ? cg.z  : cg.x,  c1v = j ? cg.w  : cg.y;
            const float c2v = j ? cg8.z : cg8.x, c3v = j ? cg8.w : cg8.y;
            const float s0v = j ? sg.z  : sg.x,  s1v = j ? sg.w  : sg.y;
            const float s2v = j ? sg8.z : sg8.x, s3v = j ? sg8.w : sg8.y;
            const float t0 = acc[n0][0], t1 = acc[n0][1];
            const float t2 = acc[n0][2], t3 = acc[n0][3];
            acc[n0][0] = t0 * c0v - acc[n1][0] * s0v;
            acc[n0][1] = t1 * c1v - acc[n1][1] * s1v;
            acc[n0][2] = t2 * c2v - acc[n1][2] * s2v;
            acc[n0][3] = t3 * c3v - acc[n1][3] * s3v;
            acc[n1][0] = acc[n1][0] * c0v + t0 * s0v;
            acc[n1][1] = acc[n1][1] * c1v + t1 * s1v;
            acc[n1][2] = acc[n1][2] * c2v + t2 * s2v;
            acc[n1][3] = acc[n1][3] * c3v + t3 * s3v;
        }
    }

    // pack z to fp16 A-fragments (acc dies -> frees regs)
    unsigned fh[16][2];
#pragma unroll
    for (int n = 0; n < 16; n++) {
        fh[n][0] = h2p(acc[n][0], acc[n][1]);
        fh[n][1] = h2p(acc[n][2], acc[n][3]);
    }

    // ---------------- GEMM2: out = z @ Q (trans B) ----------------
    float o[16][4];
#pragma unroll
    for (int n = 0; n < 16; n++)
#pragma unroll
        for (int i = 0; i < 4; i++) o[n][i] = 0.f;

#pragma unroll
    for (int kt = 0; kt < 8; kt++) {
        const unsigned a0 = fh[2 * kt][0],     a1 = fh[2 * kt][1];
        const unsigned a2 = fh[2 * kt + 1][0], a3 = fh[2 * kt + 1][1];
#pragma unroll
        for (int np = 0; np < 8; np++) {
            unsigned bh[4];
            ldsm4t(bh, su32(sQ + kt * 16 * QS + np * 16 + lbo));
            mma16816(o[2 * np],     a0, a1, a2, a3, bh[0], bh[2]);
            mma16816(o[2 * np + 1], a0, a1, a2, a3, bh[1], bh[3]);
        }
    }

    // ------- store: slot cols -> true col 16np+4u+2j+k = contiguous float4 -
    float* O0 = out + (size_t)(base + warp * 16 + g) * 128;
    float* O1 = O0 + 8 * 128;
#pragma unroll
    for (int np = 0; np < 8; np++) {
        const int col = np * 16 + 4 * u;
        *(float4*)&O0[col] = make_float4(o[2*np][0], o[2*np][1], o[2*np+1][0], o[2*np+1][1]);
        *(float4*)&O1[col] = make_float4(o[2*np][2], o[2*np][3], o[2*np+1][2], o[2*np+1][3]);
    }
}

// ---------------------------------------------------------------------------
extern "C" void kernel_launch(void* const* d_in, const int* in_sizes, int n_in,
                              void* d_out, int out_size)
{
    (void)in_sizes; (void)n_in; (void)out_size;
    const float* q    = (const float*)d_in[0];
    const float* k    = (const float*)d_in[1];
    const float* vs   = (const float*)d_in[2];
    const float* cosg = (const float*)d_in[3];
    const float* sing = (const float*)d_in[4];
    float* out = (float*)d_out;

    build_p_kernel<<<64, 128>>>(vs);
    combine1_kernel<<<256, 128>>>();
    combine2_kernel<<<128, 128>>>();
    rnrope_main<<<4096, 256>>>(q, k, cosg, sing, out);
}